// round 3
// baseline (speedup 1.0000x reference)
#include <cuda_runtime.h>
#include <math.h>

#define N_NODES   100000
#define N_EDGES   1250000
#define HID       64
#define N_RBF     32
#define N_GRAPHS  512
#define N_EXPERTS 8
#define N_LAYERS  3
#define MAX_Z     100
#define GATE_IN   72
#define G1        64
#define G2        32
#define TABLE     4096
#define CUTOFF    6.0f

// ---------------- scratch (no allocations allowed) ----------------
__device__ __align__(256) float g_x[N_NODES * HID];
__device__ __align__(256) float g_y[N_NODES * HID];
__device__ __align__(256) float g_agg[N_NODES * HID];
__device__ __align__(256) float g_tab[N_LAYERS][(TABLE + 1) * HID];
__device__ __align__(256) float g_pooled[N_GRAPHS * HID];
__device__ float g_counts[N_GRAPHS];

__device__ __forceinline__ float silu_f(float v) { return v / (1.0f + __expf(-v)); }

// ---------------- filter-network lookup table --------------------
// tab[l][i][c] = (silu(rbf(w_i) @ fW1[l].T + fb1[l]) @ fW2[l].T + fb2[l])[c]
// w_i = CUTOFF * i / TABLE, i in [0, TABLE]
__global__ void k_tables(const float* __restrict__ fW1, const float* __restrict__ fb1,
                         const float* __restrict__ fW2, const float* __restrict__ fb2) {
    int l = blockIdx.y;
    int i = blockIdx.x;
    int c = threadIdx.x;  // 0..63
    __shared__ float rbf[N_RBF];
    __shared__ float h[HID];

    float w = CUTOFF * (float)i / (float)TABLE;
    if (c < N_RBF) {
        float delta = CUTOFF / (float)(N_RBF - 1);
        float off = delta * (float)c;
        float coeff = -0.5f / (delta * delta);
        float d = w - off;
        rbf[c] = expf(coeff * d * d);
    }
    __syncthreads();

    const float* W1 = fW1 + (l * HID + c) * N_RBF;
    float acc = fb1[l * HID + c];
#pragma unroll
    for (int k = 0; k < N_RBF; k++) acc += rbf[k] * W1[k];
    h[c] = acc / (1.0f + expf(-acc));  // precise silu for the table
    __syncthreads();

    const float* W2 = fW2 + (l * HID + c) * HID;
    float acc2 = fb2[l * HID + c];
#pragma unroll
    for (int k = 0; k < HID; k++) acc2 += h[k] * W2[k];
    g_tab[l][i * HID + c] = acc2;
}

// ---------------- embedding + init --------------------------------
__global__ void k_embed(const int* __restrict__ z, const float* __restrict__ emb) {
    int idx = blockIdx.x * blockDim.x + threadIdx.x;
    if (idx >= N_NODES * HID) return;
    int n = idx >> 6, c = idx & 63;
    g_x[idx] = emb[z[n] * HID + c];
}

__global__ void k_init() {
    int idx = blockIdx.x * blockDim.x + threadIdx.x;
    if (idx < N_NODES * HID) g_agg[idx] = 0.0f;
    if (idx < N_GRAPHS * HID) g_pooled[idx] = 0.0f;
    if (idx < N_GRAPHS) g_counts[idx] = 0.0f;
}

// ---------------- y = x @ dW[l].T + db[l] -------------------------
// W staged transposed in smem: Wt[k*64+c] = dW[c*64+k]  (bank-conflict-free reads)
__global__ void k_ylinear(const float* __restrict__ dW, const float* __restrict__ db, int layer) {
    __shared__ float Wt[HID * HID];
    __shared__ float xs[4][HID];
    const float* W = dW + layer * HID * HID;
    for (int idx = threadIdx.x; idx < HID * HID; idx += blockDim.x) {
        int c = idx >> 6, k = idx & 63;
        Wt[k * HID + c] = W[idx];
    }
    __syncthreads();
    int rg = threadIdx.x >> 6;
    int c = threadIdx.x & 63;
    float bias = db[layer * HID + c];
    for (long base = (long)blockIdx.x * 4; base < N_NODES; base += (long)gridDim.x * 4) {
        long n = base + rg;
        if (n < N_NODES) xs[rg][c] = g_x[n * HID + c];
        __syncthreads();
        if (n < N_NODES) {
            float acc = bias;
#pragma unroll
            for (int k = 0; k < HID; k++) acc += xs[rg][k] * Wt[k * HID + c];
            g_y[n * HID + c] = acc;
        }
        __syncthreads();
    }
}

// ---------------- edge scatter: agg[dst] += y[src] * f(w) ---------
// One half-warp (16 lanes) per edge; lane handles 4 channels via float4.
__global__ void k_edge(const int* __restrict__ edge_index, const float* __restrict__ ew, int layer) {
    unsigned tid = blockIdx.x * blockDim.x + threadIdx.x;
    unsigned e = tid >> 4;
    int sub = threadIdx.x & 15;
    if (e >= N_EDGES) return;

    int s = __ldg(&edge_index[e]);
    int d = __ldg(&edge_index[N_EDGES + e]);
    float w = __ldg(&ew[e]);

    float t = w * ((float)TABLE / CUTOFF);
    int i0 = (int)t;
    if (i0 < 0) i0 = 0;
    if (i0 > TABLE - 1) i0 = TABLE - 1;
    float fr = t - (float)i0;

    const float4* yrow = (const float4*)&g_y[(long)s * HID];
    const float4* t0 = (const float4*)&g_tab[layer][(long)i0 * HID];
    const float4* t1 = (const float4*)&g_tab[layer][(long)(i0 + 1) * HID];

    float4 yv = __ldg(&yrow[sub]);
    float4 a = __ldg(&t0[sub]);
    float4 b = __ldg(&t1[sub]);

    float fx = a.x + fr * (b.x - a.x);
    float fy = a.y + fr * (b.y - a.y);
    float fz = a.z + fr * (b.z - a.z);
    float fw = a.w + fr * (b.w - a.w);

    float* ag = &g_agg[(long)d * HID + sub * 4];
    atomicAdd(ag + 0, yv.x * fx);
    atomicAdd(ag + 1, yv.y * fy);
    atomicAdd(ag + 2, yv.z * fz);
    atomicAdd(ag + 3, yv.w * fw);
}

// ---------------- node update: x += silu(agg@uW1.T+ub1)@uW2.T+ub2; agg = 0
__global__ void k_update(const float* __restrict__ uW1, const float* __restrict__ ub1,
                         const float* __restrict__ uW2, const float* __restrict__ ub2, int layer) {
    __shared__ float W1t[HID * HID];
    __shared__ float W2t[HID * HID];
    __shared__ float as[4][HID];
    __shared__ float hs[4][HID];
    const float* W1 = uW1 + layer * HID * HID;
    const float* W2 = uW2 + layer * HID * HID;
    for (int idx = threadIdx.x; idx < HID * HID; idx += blockDim.x) {
        int c = idx >> 6, k = idx & 63;
        W1t[k * HID + c] = W1[idx];
        W2t[k * HID + c] = W2[idx];
    }
    __syncthreads();
    int rg = threadIdx.x >> 6;
    int c = threadIdx.x & 63;
    float b1 = ub1[layer * HID + c];
    float b2 = ub2[layer * HID + c];
    for (long base = (long)blockIdx.x * 4; base < N_NODES; base += (long)gridDim.x * 4) {
        long n = base + rg;
        if (n < N_NODES) {
            as[rg][c] = g_agg[n * HID + c];
            g_agg[n * HID + c] = 0.0f;  // ready for next layer
        }
        __syncthreads();
        if (n < N_NODES) {
            float acc = b1;
#pragma unroll
            for (int k = 0; k < HID; k++) acc += as[rg][k] * W1t[k * HID + c];
            hs[rg][c] = silu_f(acc);
        }
        __syncthreads();
        if (n < N_NODES) {
            float acc = b2;
#pragma unroll
            for (int k = 0; k < HID; k++) acc += hs[rg][k] * W2t[k * HID + c];
            g_x[n * HID + c] += acc;
        }
        __syncthreads();
    }
}

// ---------------- mean pool ---------------------------------------
__global__ void k_pool(const int* __restrict__ batch) {
    int idx = blockIdx.x * blockDim.x + threadIdx.x;
    if (idx >= N_NODES * HID) return;
    int n = idx >> 6, c = idx & 63;
    int g = __ldg(&batch[n]);
    atomicAdd(&g_pooled[g * HID + c], g_x[idx]);
    if (c == 0) atomicAdd(&g_counts[g], 1.0f);
}

// ---------------- gate MLP + softmax + prediction -----------------
__global__ void k_gate(const float* __restrict__ mlip,
                       const float* __restrict__ gW1, const float* __restrict__ gb1,
                       const float* __restrict__ gW2, const float* __restrict__ gb2,
                       const float* __restrict__ gW3, const float* __restrict__ gb3,
                       float* __restrict__ out) {
    int g = blockIdx.x;   // 0..511
    int c = threadIdx.x;  // 0..63
    __shared__ float in[GATE_IN];
    __shared__ float h1[G1];
    __shared__ float h2[G2];
    __shared__ float lg[N_EXPERTS];

    float cnt = fmaxf(g_counts[g], 1.0f);
    in[c] = g_pooled[g * HID + c] / cnt;
    if (c < N_EXPERTS) in[HID + c] = mlip[g * N_EXPERTS + c];
    __syncthreads();

    float acc = gb1[c];
#pragma unroll
    for (int k = 0; k < GATE_IN; k++) acc += in[k] * gW1[c * GATE_IN + k];
    h1[c] = fmaxf(acc, 0.0f);
    __syncthreads();

    if (c < G2) {
        float a2 = gb2[c];
#pragma unroll
        for (int k = 0; k < G1; k++) a2 += h1[k] * gW2[c * G1 + k];
        h2[c] = fmaxf(a2, 0.0f);
    }
    __syncthreads();

    if (c < N_EXPERTS) {
        float a3 = gb3[c];
#pragma unroll
        for (int k = 0; k < G2; k++) a3 += h2[k] * gW3[c * G2 + k];
        lg[c] = a3;
        out[g * N_EXPERTS + c] = a3;  // logits
    }
    __syncthreads();

    if (c == 0) {
        float m = lg[0];
        for (int k = 1; k < N_EXPERTS; k++) m = fmaxf(m, lg[k]);
        float wts[N_EXPERTS];
        float ssum = 0.0f;
        for (int k = 0; k < N_EXPERTS; k++) { wts[k] = expf(lg[k] - m); ssum += wts[k]; }
        float pred = 0.0f;
        for (int k = 0; k < N_EXPERTS; k++) {
            float wv = wts[k] / ssum;
            out[N_GRAPHS * N_EXPERTS + g * N_EXPERTS + k] = wv;  // weights
            pred += mlip[g * N_EXPERTS + k] * wv;
        }
        out[2 * N_GRAPHS * N_EXPERTS + g] = pred;  // prediction
    }
}

// ---------------- launch ------------------------------------------
extern "C" void kernel_launch(void* const* d_in, const int* in_sizes, int n_in,
                              void* d_out, int out_size) {
    const int* z = (const int*)d_in[0];
    const int* edge_index = (const int*)d_in[1];
    const float* ew = (const float*)d_in[2];
    const int* batch = (const int*)d_in[3];
    const float* mlip = (const float*)d_in[4];
    const float* emb = (const float*)d_in[5];
    const float* fW1 = (const float*)d_in[6];
    const float* fb1 = (const float*)d_in[7];
    const float* fW2 = (const float*)d_in[8];
    const float* fb2 = (const float*)d_in[9];
    const float* dW = (const float*)d_in[10];
    const float* db = (const float*)d_in[11];
    const float* uW1 = (const float*)d_in[12];
    const float* ub1 = (const float*)d_in[13];
    const float* uW2 = (const float*)d_in[14];
    const float* ub2 = (const float*)d_in[15];
    const float* gW1 = (const float*)d_in[16];
    const float* gb1 = (const float*)d_in[17];
    const float* gW2 = (const float*)d_in[18];
    const float* gb2 = (const float*)d_in[19];
    const float* gW3 = (const float*)d_in[20];
    const float* gb3 = (const float*)d_in[21];
    float* out = (float*)d_out;

    // filter tables (3 layers x 4097 entries)
    {
        dim3 grid(TABLE + 1, N_LAYERS);
        k_tables<<<grid, HID>>>(fW1, fb1, fW2, fb2);
    }
    // embedding + zero scratch
    {
        int total = N_NODES * HID;
        k_embed<<<(total + 255) / 256, 256>>>(z, emb);
        k_init<<<(total + 255) / 256, 256>>>();
    }

    for (int l = 0; l < N_LAYERS; l++) {
        k_ylinear<<<2048, 256>>>(dW, db, l);
        {
            long threads = (long)N_EDGES * 16;
            int blocks = (int)((threads + 255) / 256);
            k_edge<<<blocks, 256>>>(edge_index, ew, l);
        }
        k_update<<<2048, 256>>>(uW1, ub1, uW2, ub2, l);
    }

    k_pool<<<(N_NODES * HID + 255) / 256, 256>>>(batch);
    k_gate<<<N_GRAPHS, HID>>>(mlip, gW1, gb1, gW2, gb2, gW3, gb3, out);
}

// round 4
// speedup vs baseline: 1.8017x; 1.8017x over previous
#include <cuda_runtime.h>
#include <math.h>

#define N_NODES   100000
#define N_EDGES   1250000
#define HID       64
#define N_RBF     32
#define N_GRAPHS  512
#define N_EXPERTS 8
#define N_LAYERS  3
#define MAX_Z     100
#define GATE_IN   72
#define G1        64
#define G2        32
#define TABLE     4096
#define CUTOFF    6.0f
#define PITCH     68   // smem row pitch (floats): mult of 4 for float4, not mult of 32

// ---------------- scratch (no allocations allowed) ----------------
__device__ __align__(256) float g_x[N_NODES * HID];
__device__ __align__(256) float g_y[N_NODES * HID];
__device__ __align__(256) float g_agg[N_NODES * HID];
// per table row: [0:64) = value, [64:128) = delta to next row
__device__ __align__(256) float g_tabc[N_LAYERS][(TABLE + 1) * 128];
__device__ __align__(256) float g_pooled[N_GRAPHS * HID];
__device__ float g_counts[N_GRAPHS];

__device__ __forceinline__ float silu_f(float v) { return v / (1.0f + __expf(-v)); }

// ---------------- filter-network lookup table --------------------
__global__ void k_tables(const float* __restrict__ fW1, const float* __restrict__ fb1,
                         const float* __restrict__ fW2, const float* __restrict__ fb2) {
    int l = blockIdx.y;
    int i = blockIdx.x;
    int c = threadIdx.x;  // 0..63
    __shared__ float rbf[N_RBF];
    __shared__ float h[HID];

    float w = CUTOFF * (float)i / (float)TABLE;
    if (c < N_RBF) {
        float delta = CUTOFF / (float)(N_RBF - 1);
        float off = delta * (float)c;
        float coeff = -0.5f / (delta * delta);
        float d = w - off;
        rbf[c] = expf(coeff * d * d);
    }
    __syncthreads();

    const float* W1 = fW1 + (l * HID + c) * N_RBF;
    float acc = fb1[l * HID + c];
#pragma unroll
    for (int k = 0; k < N_RBF; k++) acc += rbf[k] * W1[k];
    h[c] = acc / (1.0f + expf(-acc));
    __syncthreads();

    const float* W2 = fW2 + (l * HID + c) * HID;
    float acc2 = fb2[l * HID + c];
#pragma unroll
    for (int k = 0; k < HID; k++) acc2 += h[k] * W2[k];
    g_tabc[l][i * 128 + c] = acc2;
}

// delta rows: tabc[l][i][64+c] = val[i+1][c] - val[i][c]
__global__ void k_tabdel() {
    int idx = blockIdx.x * blockDim.x + threadIdx.x;
    if (idx >= N_LAYERS * TABLE * HID) return;
    int c = idx & 63;
    int i = (idx >> 6) % TABLE;
    int l = idx / (TABLE * HID);
    g_tabc[l][i * 128 + 64 + c] = g_tabc[l][(i + 1) * 128 + c] - g_tabc[l][i * 128 + c];
}

// ---------------- embedding + init --------------------------------
__global__ void k_embed(const int* __restrict__ z, const float* __restrict__ emb) {
    int idx = blockIdx.x * blockDim.x + threadIdx.x;
    if (idx >= N_NODES * HID) return;
    int n = idx >> 6, c = idx & 63;
    g_x[idx] = emb[z[n] * HID + c];
}

__global__ void k_init() {
    int idx = blockIdx.x * blockDim.x + threadIdx.x;
    if (idx < N_NODES * HID) g_agg[idx] = 0.0f;
    if (idx < N_GRAPHS * HID) g_pooled[idx] = 0.0f;
    if (idx < N_GRAPHS) g_counts[idx] = 0.0f;
}

// ---------------- helpers for register-blocked node GEMMs ---------
// Load W (64x64, torch [out,in]) transposed into smem: Wt[k][c] = W[c*64+k].
// Coalesced global float4 reads along k; smem writes ~8-way conflicted (one-time).
__device__ __forceinline__ void load_w_t(const float* __restrict__ W, float (*Wt)[PITCH], int tid) {
#pragma unroll
    for (int it = 0; it < 4; it++) {
        int idx = it * 256 + tid;   // 0..1023
        int kq = idx & 15;
        int c = idx >> 4;           // 0..63
        float4 v = *(const float4*)&W[c * HID + kq * 4];
        Wt[kq * 4 + 0][c] = v.x;
        Wt[kq * 4 + 1][c] = v.y;
        Wt[kq * 4 + 2][c] = v.z;
        Wt[kq * 4 + 3][c] = v.w;
    }
}

// ---------------- y = x @ dW[l].T + db[l] -------------------------
// 64-node x 64-ch tile per block; thread computes 4x4 register tile.
__global__ __launch_bounds__(256) void k_ylinear(const float* __restrict__ dW,
                                                 const float* __restrict__ db, int layer) {
    __shared__ float Wt[HID][PITCH];
    __shared__ float xT[HID][PITCH];  // xT[k][n]
    int tid = threadIdx.x;
    load_w_t(dW + layer * HID * HID, Wt, tid);

    int node0 = blockIdx.x * 64;
#pragma unroll
    for (int it = 0; it < 4; it++) {
        int idx = it * 256 + tid;
        int q = idx & 15;
        int n = idx >> 4;
        if (node0 + n < N_NODES) {
            float4 v = *(const float4*)&g_x[(size_t)(node0 + n) * HID + q * 4];
            xT[q * 4 + 0][n] = v.x;
            xT[q * 4 + 1][n] = v.y;
            xT[q * 4 + 2][n] = v.z;
            xT[q * 4 + 3][n] = v.w;
        }
    }
    __syncthreads();

    int cg = tid & 15, ng = tid >> 4;
    float acc[4][4];
#pragma unroll
    for (int i = 0; i < 4; i++)
#pragma unroll
        for (int j = 0; j < 4; j++) acc[i][j] = 0.0f;

#pragma unroll 16
    for (int k = 0; k < HID; k++) {
        float4 b = *(const float4*)&Wt[k][cg * 4];
        float4 a = *(const float4*)&xT[k][ng * 4];
        acc[0][0] += a.x * b.x; acc[0][1] += a.x * b.y; acc[0][2] += a.x * b.z; acc[0][3] += a.x * b.w;
        acc[1][0] += a.y * b.x; acc[1][1] += a.y * b.y; acc[1][2] += a.y * b.z; acc[1][3] += a.y * b.w;
        acc[2][0] += a.z * b.x; acc[2][1] += a.z * b.y; acc[2][2] += a.z * b.z; acc[2][3] += a.z * b.w;
        acc[3][0] += a.w * b.x; acc[3][1] += a.w * b.y; acc[3][2] += a.w * b.z; acc[3][3] += a.w * b.w;
    }

    float4 bias = *(const float4*)&db[layer * HID + cg * 4];
#pragma unroll
    for (int i = 0; i < 4; i++) {
        int n = node0 + ng * 4 + i;
        if (n < N_NODES) {
            float4 o;
            o.x = acc[i][0] + bias.x;
            o.y = acc[i][1] + bias.y;
            o.z = acc[i][2] + bias.z;
            o.w = acc[i][3] + bias.w;
            *(float4*)&g_y[(size_t)n * HID + cg * 4] = o;
        }
    }
}

// ---------------- edge scatter: agg[dst] += y[src] * f(w) ---------
// 4 lanes per edge; lane handles 4 float4 chunks; single-FMA lerp via
// precomputed delta rows; vectorized red.global.add.v4.f32.
__global__ __launch_bounds__(256) void k_edge(const int* __restrict__ edge_index,
                                              const float* __restrict__ ew, int layer) {
    unsigned t = blockIdx.x * blockDim.x + threadIdx.x;
    unsigned e = t >> 2;
    int sub = t & 3;
    if (e >= N_EDGES) return;

    int s = __ldg(&edge_index[e]);
    int d = __ldg(&edge_index[N_EDGES + e]);
    float w = __ldg(&ew[e]);

    float tt = w * ((float)TABLE / CUTOFF);
    int i0 = (int)tt;
    if (i0 < 0) i0 = 0;
    if (i0 > TABLE - 1) i0 = TABLE - 1;
    float fr = tt - (float)i0;

    const float4* yrow = (const float4*)&g_y[(size_t)s * HID];
    const float4* trow = (const float4*)&g_tabc[layer][(size_t)i0 * 128];  // [0:16)=val4, [16:32)=del4
    float* ag = &g_agg[(size_t)d * HID];

#pragma unroll
    for (int j = 0; j < 4; j++) {
        int ch = sub + j * 4;  // 0..15
        float4 yv = __ldg(&yrow[ch]);
        float4 v = __ldg(&trow[ch]);
        float4 dl = __ldg(&trow[16 + ch]);
        float mx = yv.x * fmaf(fr, dl.x, v.x);
        float my = yv.y * fmaf(fr, dl.y, v.y);
        float mz = yv.z * fmaf(fr, dl.z, v.z);
        float mw = yv.w * fmaf(fr, dl.w, v.w);
        asm volatile("red.global.add.v4.f32 [%0], {%1, %2, %3, %4};"
                     :: "l"(ag + ch * 4), "f"(mx), "f"(my), "f"(mz), "f"(mw)
                     : "memory");
    }
}

// ---------------- node update: x += silu(agg@uW1.T+ub1)@uW2.T+ub2; agg=0
__global__ __launch_bounds__(256) void k_update(const float* __restrict__ uW1,
                                                const float* __restrict__ ub1,
                                                const float* __restrict__ uW2,
                                                const float* __restrict__ ub2, int layer) {
    __shared__ float Wt[HID][PITCH];  // W1t, then reused for W2t
    __shared__ float T[HID][PITCH];   // aggT, then reused for hT
    int tid = threadIdx.x;
    load_w_t(uW1 + layer * HID * HID, Wt, tid);

    int node0 = blockIdx.x * 64;
#pragma unroll
    for (int it = 0; it < 4; it++) {
        int idx = it * 256 + tid;
        int q = idx & 15;
        int n = idx >> 4;
        if (node0 + n < N_NODES) {
            float4 v = *(const float4*)&g_agg[(size_t)(node0 + n) * HID + q * 4];
            float4 zr = make_float4(0.f, 0.f, 0.f, 0.f);
            *(float4*)&g_agg[(size_t)(node0 + n) * HID + q * 4] = zr;  // ready for next layer
            T[q * 4 + 0][n] = v.x;
            T[q * 4 + 1][n] = v.y;
            T[q * 4 + 2][n] = v.z;
            T[q * 4 + 3][n] = v.w;
        }
    }
    __syncthreads();

    int cg = tid & 15, ng = tid >> 4;
    float acc[4][4];
#pragma unroll
    for (int i = 0; i < 4; i++)
#pragma unroll
        for (int j = 0; j < 4; j++) acc[i][j] = 0.0f;

#pragma unroll 16
    for (int k = 0; k < HID; k++) {
        float4 b = *(const float4*)&Wt[k][cg * 4];
        float4 a = *(const float4*)&T[k][ng * 4];
        acc[0][0] += a.x * b.x; acc[0][1] += a.x * b.y; acc[0][2] += a.x * b.z; acc[0][3] += a.x * b.w;
        acc[1][0] += a.y * b.x; acc[1][1] += a.y * b.y; acc[1][2] += a.y * b.z; acc[1][3] += a.y * b.w;
        acc[2][0] += a.z * b.x; acc[2][1] += a.z * b.y; acc[2][2] += a.z * b.z; acc[2][3] += a.z * b.w;
        acc[3][0] += a.w * b.x; acc[3][1] += a.w * b.y; acc[3][2] += a.w * b.z; acc[3][3] += a.w * b.w;
    }

    float4 b1 = *(const float4*)&ub1[layer * HID + cg * 4];
    float h[4][4];
#pragma unroll
    for (int i = 0; i < 4; i++) {
        h[i][0] = silu_f(acc[i][0] + b1.x);
        h[i][1] = silu_f(acc[i][1] + b1.y);
        h[i][2] = silu_f(acc[i][2] + b1.z);
        h[i][3] = silu_f(acc[i][3] + b1.w);
    }
    __syncthreads();  // all reads of T and Wt complete

    // hT[c][n] = h  (overwrite T); reload Wt with W2 transposed
#pragma unroll
    for (int i = 0; i < 4; i++)
#pragma unroll
        for (int j = 0; j < 4; j++) T[cg * 4 + j][ng * 4 + i] = h[i][j];
    load_w_t(uW2 + layer * HID * HID, Wt, tid);
    __syncthreads();

#pragma unroll
    for (int i = 0; i < 4; i++)
#pragma unroll
        for (int j = 0; j < 4; j++) acc[i][j] = 0.0f;

#pragma unroll 16
    for (int k = 0; k < HID; k++) {
        float4 b = *(const float4*)&Wt[k][cg * 4];
        float4 a = *(const float4*)&T[k][ng * 4];
        acc[0][0] += a.x * b.x; acc[0][1] += a.x * b.y; acc[0][2] += a.x * b.z; acc[0][3] += a.x * b.w;
        acc[1][0] += a.y * b.x; acc[1][1] += a.y * b.y; acc[1][2] += a.y * b.z; acc[1][3] += a.y * b.w;
        acc[2][0] += a.z * b.x; acc[2][1] += a.z * b.y; acc[2][2] += a.z * b.z; acc[2][3] += a.z * b.w;
        acc[3][0] += a.w * b.x; acc[3][1] += a.w * b.y; acc[3][2] += a.w * b.z; acc[3][3] += a.w * b.w;
    }

    float4 b2 = *(const float4*)&ub2[layer * HID + cg * 4];
#pragma unroll
    for (int i = 0; i < 4; i++) {
        int n = node0 + ng * 4 + i;
        if (n < N_NODES) {
            float4 xv = *(const float4*)&g_x[(size_t)n * HID + cg * 4];
            xv.x += acc[i][0] + b2.x;
            xv.y += acc[i][1] + b2.y;
            xv.z += acc[i][2] + b2.z;
            xv.w += acc[i][3] + b2.w;
            *(float4*)&g_x[(size_t)n * HID + cg * 4] = xv;
        }
    }
}

// ---------------- mean pool (batch is sorted: segmented flush) -----
__global__ void k_pool(const int* __restrict__ batch) {
    int tid = threadIdx.x;
    int c = tid & 63;
    int grp = tid >> 6;  // 0..3
    long base = (long)blockIdx.x * 64 + grp * 16;
    if (base >= N_NODES) return;

    float acc = 0.0f;
    int cur = -1;
    for (int i = 0; i < 16; i++) {
        long n = base + i;
        if (n >= N_NODES) break;
        int g = __ldg(&batch[n]);
        if (g != cur) {
            if (cur >= 0) atomicAdd(&g_pooled[cur * HID + c], acc);
            cur = g;
            acc = 0.0f;
        }
        acc += g_x[n * HID + c];
    }
    if (cur >= 0) atomicAdd(&g_pooled[cur * HID + c], acc);

    if (c == 0) {
        float cnt = 0.0f;
        int cg2 = -1;
        for (int i = 0; i < 16; i++) {
            long n = base + i;
            if (n >= N_NODES) break;
            int g = __ldg(&batch[n]);
            if (g != cg2) {
                if (cg2 >= 0) atomicAdd(&g_counts[cg2], cnt);
                cg2 = g;
                cnt = 0.0f;
            }
            cnt += 1.0f;
        }
        if (cg2 >= 0) atomicAdd(&g_counts[cg2], cnt);
    }
}

// ---------------- gate MLP + softmax + prediction -----------------
__global__ void k_gate(const float* __restrict__ mlip,
                       const float* __restrict__ gW1, const float* __restrict__ gb1,
                       const float* __restrict__ gW2, const float* __restrict__ gb2,
                       const float* __restrict__ gW3, const float* __restrict__ gb3,
                       float* __restrict__ out) {
    int g = blockIdx.x;
    int c = threadIdx.x;
    __shared__ float in[GATE_IN];
    __shared__ float h1[G1];
    __shared__ float h2[G2];
    __shared__ float lg[N_EXPERTS];

    float cnt = fmaxf(g_counts[g], 1.0f);
    in[c] = g_pooled[g * HID + c] / cnt;
    if (c < N_EXPERTS) in[HID + c] = mlip[g * N_EXPERTS + c];
    __syncthreads();

    float acc = gb1[c];
#pragma unroll
    for (int k = 0; k < GATE_IN; k++) acc += in[k] * gW1[c * GATE_IN + k];
    h1[c] = fmaxf(acc, 0.0f);
    __syncthreads();

    if (c < G2) {
        float a2 = gb2[c];
#pragma unroll
        for (int k = 0; k < G1; k++) a2 += h1[k] * gW2[c * G1 + k];
        h2[c] = fmaxf(a2, 0.0f);
    }
    __syncthreads();

    if (c < N_EXPERTS) {
        float a3 = gb3[c];
#pragma unroll
        for (int k = 0; k < G2; k++) a3 += h2[k] * gW3[c * G2 + k];
        lg[c] = a3;
        out[g * N_EXPERTS + c] = a3;  // logits
    }
    __syncthreads();

    if (c == 0) {
        float m = lg[0];
        for (int k = 1; k < N_EXPERTS; k++) m = fmaxf(m, lg[k]);
        float wts[N_EXPERTS];
        float ssum = 0.0f;
        for (int k = 0; k < N_EXPERTS; k++) { wts[k] = expf(lg[k] - m); ssum += wts[k]; }
        float pred = 0.0f;
        for (int k = 0; k < N_EXPERTS; k++) {
            float wv = wts[k] / ssum;
            out[N_GRAPHS * N_EXPERTS + g * N_EXPERTS + k] = wv;  // weights
            pred += mlip[g * N_EXPERTS + k] * wv;
        }
        out[2 * N_GRAPHS * N_EXPERTS + g] = pred;  // prediction
    }
}

// ---------------- launch ------------------------------------------
extern "C" void kernel_launch(void* const* d_in, const int* in_sizes, int n_in,
                              void* d_out, int out_size) {
    const int* z = (const int*)d_in[0];
    const int* edge_index = (const int*)d_in[1];
    const float* ew = (const float*)d_in[2];
    const int* batch = (const int*)d_in[3];
    const float* mlip = (const float*)d_in[4];
    const float* emb = (const float*)d_in[5];
    const float* fW1 = (const float*)d_in[6];
    const float* fb1 = (const float*)d_in[7];
    const float* fW2 = (const float*)d_in[8];
    const float* fb2 = (const float*)d_in[9];
    const float* dW = (const float*)d_in[10];
    const float* db = (const float*)d_in[11];
    const float* uW1 = (const float*)d_in[12];
    const float* ub1 = (const float*)d_in[13];
    const float* uW2 = (const float*)d_in[14];
    const float* ub2 = (const float*)d_in[15];
    const float* gW1 = (const float*)d_in[16];
    const float* gb1 = (const float*)d_in[17];
    const float* gW2 = (const float*)d_in[18];
    const float* gb2 = (const float*)d_in[19];
    const float* gW3 = (const float*)d_in[20];
    const float* gb3 = (const float*)d_in[21];
    float* out = (float*)d_out;

    // filter tables + deltas
    {
        dim3 grid(TABLE + 1, N_LAYERS);
        k_tables<<<grid, HID>>>(fW1, fb1, fW2, fb2);
        int total = N_LAYERS * TABLE * HID;
        k_tabdel<<<(total + 255) / 256, 256>>>();
    }
    // embedding + zero scratch
    {
        int total = N_NODES * HID;
        k_embed<<<(total + 255) / 256, 256>>>(z, emb);
        k_init<<<(total + 255) / 256, 256>>>();
    }

    int node_blocks = (N_NODES + 63) / 64;  // 1563
    for (int l = 0; l < N_LAYERS; l++) {
        k_ylinear<<<node_blocks, 256>>>(dW, db, l);
        {
            long threads = (long)N_EDGES * 4;
            int blocks = (int)((threads + 255) / 256);
            k_edge<<<blocks, 256>>>(edge_index, ew, l);
        }
        k_update<<<node_blocks, 256>>>(uW1, ub1, uW2, ub2, l);
    }

    k_pool<<<node_blocks, 256>>>(batch);
    k_gate<<<N_GRAPHS, HID>>>(mlip, gW1, gb1, gW2, gb2, gW3, gb3, out);
}

// round 5
// speedup vs baseline: 1.9483x; 1.0814x over previous
#include <cuda_runtime.h>
#include <math.h>

#define N_NODES   100000
#define N_EDGES   1250000
#define HID       64
#define N_RBF     32
#define N_GRAPHS  512
#define N_EXPERTS 8
#define N_LAYERS  3
#define MAX_Z     100
#define GATE_IN   72
#define G1        64
#define G2        32
#define TABLE     4096
#define CUTOFF    6.0f
#define PITCH     68   // smem row pitch (floats): mult of 4 for float4, not mult of 32

// ---------------- scratch (no allocations allowed) ----------------
__device__ __align__(256) float g_x[N_NODES * HID];
__device__ __align__(256) float g_y[N_NODES * HID];
__device__ __align__(256) float g_agg[N_NODES * HID];
// per table row: [0:64) = value, [64:128) = delta to next row
__device__ __align__(256) float g_tabc[N_LAYERS][(TABLE + 1) * 128];
__device__ __align__(256) float g_pooled[N_GRAPHS * HID];
__device__ float g_counts[N_GRAPHS];
// dst-sorted CSR
__device__ __align__(256) int   g_hist[N_NODES];
__device__ __align__(256) int   g_rowptr[N_NODES + 1];
__device__ __align__(256) int   g_cursor[N_NODES];
__device__ __align__(256) uint2 g_col[N_EDGES];   // .x = src | (i0<<17), .y = bits(fr)

__device__ __forceinline__ float silu_f(float v) { return v / (1.0f + __expf(-v)); }

// ---------------- filter-network lookup table --------------------
__global__ void k_tables(const float* __restrict__ fW1, const float* __restrict__ fb1,
                         const float* __restrict__ fW2, const float* __restrict__ fb2) {
    int l = blockIdx.y;
    int i = blockIdx.x;
    int c = threadIdx.x;  // 0..63
    __shared__ float rbf[N_RBF];
    __shared__ float h[HID];

    float w = CUTOFF * (float)i / (float)TABLE;
    if (c < N_RBF) {
        float delta = CUTOFF / (float)(N_RBF - 1);
        float off = delta * (float)c;
        float coeff = -0.5f / (delta * delta);
        float d = w - off;
        rbf[c] = expf(coeff * d * d);
    }
    __syncthreads();

    const float* W1 = fW1 + (l * HID + c) * N_RBF;
    float acc = fb1[l * HID + c];
#pragma unroll
    for (int k = 0; k < N_RBF; k++) acc += rbf[k] * W1[k];
    h[c] = acc / (1.0f + expf(-acc));
    __syncthreads();

    const float* W2 = fW2 + (l * HID + c) * HID;
    float acc2 = fb2[l * HID + c];
#pragma unroll
    for (int k = 0; k < HID; k++) acc2 += h[k] * W2[k];
    g_tabc[l][i * 128 + c] = acc2;
}

__global__ void k_tabdel() {
    int idx = blockIdx.x * blockDim.x + threadIdx.x;
    if (idx >= N_LAYERS * TABLE * HID) return;
    int c = idx & 63;
    int i = (idx >> 6) % TABLE;
    int l = idx / (TABLE * HID);
    g_tabc[l][i * 128 + 64 + c] = g_tabc[l][(i + 1) * 128 + c] - g_tabc[l][i * 128 + c];
}

// ---------------- per-launch zeroing ------------------------------
__global__ void k_zero() {
    int idx = blockIdx.x * blockDim.x + threadIdx.x;
    if (idx < N_NODES) g_hist[idx] = 0;
    if (idx < N_GRAPHS * HID) g_pooled[idx] = 0.0f;
    if (idx < N_GRAPHS) g_counts[idx] = 0.0f;
}

// ---------------- CSR build ---------------------------------------
__global__ void k_hist(const int* __restrict__ edge_index) {
    int e = blockIdx.x * blockDim.x + threadIdx.x;
    if (e >= N_EDGES) return;
    atomicAdd(&g_hist[edge_index[N_EDGES + e]], 1);
}

__global__ __launch_bounds__(1024) void k_scan() {
    __shared__ int sums[1024];
    const int CH = (N_NODES + 1023) / 1024;  // 98
    int t = threadIdx.x;
    int begin = t * CH;
    int end = begin + CH; if (end > N_NODES) end = N_NODES;
    int s = 0;
    for (int i = begin; i < end; i++) s += g_hist[i];
    sums[t] = s;
    __syncthreads();
    for (int off = 1; off < 1024; off <<= 1) {
        int v = (t >= off) ? sums[t - off] : 0;
        __syncthreads();
        sums[t] += v;
        __syncthreads();
    }
    int run = (t > 0) ? sums[t - 1] : 0;
    for (int i = begin; i < end; i++) {
        g_rowptr[i] = run;
        g_cursor[i] = run;
        run += g_hist[i];
    }
    if (t == 1023) g_rowptr[N_NODES] = N_EDGES;
}

__global__ void k_scatter(const int* __restrict__ edge_index, const float* __restrict__ ew) {
    int e = blockIdx.x * blockDim.x + threadIdx.x;
    if (e >= N_EDGES) return;
    int src = edge_index[e];
    int dst = edge_index[N_EDGES + e];
    float w = __ldg(&ew[e]);
    float tt = w * ((float)TABLE / CUTOFF);
    int i0 = (int)tt;
    if (i0 < 0) i0 = 0;
    if (i0 > TABLE - 1) i0 = TABLE - 1;
    float fr = tt - (float)i0;
    int pos = atomicAdd(&g_cursor[dst], 1);
    g_col[pos] = make_uint2((unsigned)src | ((unsigned)i0 << 17), __float_as_uint(fr));
}

// ---------------- helpers for register-blocked node GEMMs ---------
__device__ __forceinline__ void load_w_t(const float* __restrict__ W, float (*Wt)[PITCH], int tid) {
#pragma unroll
    for (int it = 0; it < 4; it++) {
        int idx = it * 256 + tid;   // 0..1023
        int kq = idx & 15;
        int c = idx >> 4;           // 0..63
        float4 v = *(const float4*)&W[c * HID + kq * 4];
        Wt[kq * 4 + 0][c] = v.x;
        Wt[kq * 4 + 1][c] = v.y;
        Wt[kq * 4 + 2][c] = v.z;
        Wt[kq * 4 + 3][c] = v.w;
    }
}

#define GEMM64(acc, T, Wt, cg, ng)                                                                     \
    _Pragma("unroll 16") for (int k = 0; k < HID; k++) {                                               \
        float4 b = *(const float4*)&Wt[k][cg * 4];                                                     \
        float4 a = *(const float4*)&T[k][ng * 4];                                                      \
        acc[0][0] += a.x * b.x; acc[0][1] += a.x * b.y; acc[0][2] += a.x * b.z; acc[0][3] += a.x * b.w; \
        acc[1][0] += a.y * b.x; acc[1][1] += a.y * b.y; acc[1][2] += a.y * b.z; acc[1][3] += a.y * b.w; \
        acc[2][0] += a.z * b.x; acc[2][1] += a.z * b.y; acc[2][2] += a.z * b.z; acc[2][3] += a.z * b.w; \
        acc[3][0] += a.w * b.x; acc[3][1] += a.w * b.y; acc[3][2] += a.w * b.z; acc[3][3] += a.w * b.w; \
    }

// ---------------- layer 0: x = emb[z]; y = x @ dW[0].T + db[0] ----
__global__ __launch_bounds__(256) void k_embed_ylinear(const int* __restrict__ z,
                                                       const float* __restrict__ emb,
                                                       const float* __restrict__ dW,
                                                       const float* __restrict__ db) {
    __shared__ float Wt[HID][PITCH];
    __shared__ float xT[HID][PITCH];
    int tid = threadIdx.x;
    load_w_t(dW, Wt, tid);

    int node0 = blockIdx.x * 64;
#pragma unroll
    for (int it = 0; it < 4; it++) {
        int idx = it * 256 + tid;
        int q = idx & 15;
        int n = idx >> 4;
        if (node0 + n < N_NODES) {
            int zz = __ldg(&z[node0 + n]);
            float4 v = *(const float4*)&emb[zz * HID + q * 4];
            *(float4*)&g_x[(size_t)(node0 + n) * HID + q * 4] = v;
            xT[q * 4 + 0][n] = v.x;
            xT[q * 4 + 1][n] = v.y;
            xT[q * 4 + 2][n] = v.z;
            xT[q * 4 + 3][n] = v.w;
        }
    }
    __syncthreads();

    int cg = tid & 15, ng = tid >> 4;
    float acc[4][4];
#pragma unroll
    for (int i = 0; i < 4; i++)
#pragma unroll
        for (int j = 0; j < 4; j++) acc[i][j] = 0.0f;
    GEMM64(acc, xT, Wt, cg, ng);

    float4 bias = *(const float4*)&db[cg * 4];
#pragma unroll
    for (int i = 0; i < 4; i++) {
        int n = node0 + ng * 4 + i;
        if (n < N_NODES) {
            float4 o;
            o.x = acc[i][0] + bias.x;
            o.y = acc[i][1] + bias.y;
            o.z = acc[i][2] + bias.z;
            o.w = acc[i][3] + bias.w;
            *(float4*)&g_y[(size_t)n * HID + cg * 4] = o;
        }
    }
}

// ---------------- aggregation: warp per dst node, no atomics ------
__global__ __launch_bounds__(256) void k_agg(int layer) {
    int node = (blockIdx.x * 256 + threadIdx.x) >> 5;
    int lane = threadIdx.x & 31;
    if (node >= N_NODES) return;
    int beg = g_rowptr[node];
    int end = g_rowptr[node + 1];
    const float* tab = g_tabc[layer];

    float2 acc = make_float2(0.0f, 0.0f);
    uint2 rec;
    if (beg < end) rec = __ldg(&g_col[beg]);
    for (int p = beg; p < end; p++) {
        uint2 cur = rec;
        if (p + 1 < end) rec = __ldg(&g_col[p + 1]);
        float fr = __uint_as_float(cur.y);
        int src = (int)(cur.x & 0x1FFFFu);
        int i0 = (int)(cur.x >> 17);
        float2 yv = *(const float2*)&g_y[(size_t)src * HID + lane * 2];
        float2 v = *(const float2*)&tab[(size_t)i0 * 128 + lane * 2];
        float2 dl = *(const float2*)&tab[(size_t)i0 * 128 + 64 + lane * 2];
        acc.x = fmaf(yv.x, fmaf(fr, dl.x, v.x), acc.x);
        acc.y = fmaf(yv.y, fmaf(fr, dl.y, v.y), acc.y);
    }
    *(float2*)&g_agg[(size_t)node * HID + lane * 2] = acc;
}

// -------- node update (+ fused next-layer y GEMM when !LAST) ------
template <bool LAST>
__global__ __launch_bounds__(256) void k_update(const float* __restrict__ uW1,
                                                const float* __restrict__ ub1,
                                                const float* __restrict__ uW2,
                                                const float* __restrict__ ub2,
                                                const float* __restrict__ dWn,
                                                const float* __restrict__ dbn, int layer) {
    __shared__ float Wt[HID][PITCH];
    __shared__ float T[HID][PITCH];
    int tid = threadIdx.x;
    load_w_t(uW1 + layer * HID * HID, Wt, tid);

    int node0 = blockIdx.x * 64;
#pragma unroll
    for (int it = 0; it < 4; it++) {
        int idx = it * 256 + tid;
        int q = idx & 15;
        int n = idx >> 4;
        if (node0 + n < N_NODES) {
            float4 v = *(const float4*)&g_agg[(size_t)(node0 + n) * HID + q * 4];
            T[q * 4 + 0][n] = v.x;
            T[q * 4 + 1][n] = v.y;
            T[q * 4 + 2][n] = v.z;
            T[q * 4 + 3][n] = v.w;
        }
    }
    __syncthreads();

    int cg = tid & 15, ng = tid >> 4;
    float acc[4][4];
#pragma unroll
    for (int i = 0; i < 4; i++)
#pragma unroll
        for (int j = 0; j < 4; j++) acc[i][j] = 0.0f;
    GEMM64(acc, T, Wt, cg, ng);

    float4 b1 = *(const float4*)&ub1[layer * HID + cg * 4];
    float h[4][4];
#pragma unroll
    for (int i = 0; i < 4; i++) {
        h[i][0] = silu_f(acc[i][0] + b1.x);
        h[i][1] = silu_f(acc[i][1] + b1.y);
        h[i][2] = silu_f(acc[i][2] + b1.z);
        h[i][3] = silu_f(acc[i][3] + b1.w);
    }
    __syncthreads();

#pragma unroll
    for (int i = 0; i < 4; i++)
#pragma unroll
        for (int j = 0; j < 4; j++) T[cg * 4 + j][ng * 4 + i] = h[i][j];
    load_w_t(uW2 + layer * HID * HID, Wt, tid);
    __syncthreads();

#pragma unroll
    for (int i = 0; i < 4; i++)
#pragma unroll
        for (int j = 0; j < 4; j++) acc[i][j] = 0.0f;
    GEMM64(acc, T, Wt, cg, ng);

    // x_new = x + delta + b2 ; write g_x; keep x_new in registers
    float4 b2 = *(const float4*)&ub2[layer * HID + cg * 4];
    float xn[4][4];
#pragma unroll
    for (int i = 0; i < 4; i++) {
        int n = node0 + ng * 4 + i;
        if (n < N_NODES) {
            float4 xv = *(const float4*)&g_x[(size_t)n * HID + cg * 4];
            xn[i][0] = xv.x + acc[i][0] + b2.x;
            xn[i][1] = xv.y + acc[i][1] + b2.y;
            xn[i][2] = xv.z + acc[i][2] + b2.z;
            xn[i][3] = xv.w + acc[i][3] + b2.w;
            float4 o = make_float4(xn[i][0], xn[i][1], xn[i][2], xn[i][3]);
            *(float4*)&g_x[(size_t)n * HID + cg * 4] = o;
        }
    }

    if (!LAST) {
        // stage x_new transposed, load next dW, GEMM -> g_y
        __syncthreads();
#pragma unroll
        for (int i = 0; i < 4; i++)
#pragma unroll
            for (int j = 0; j < 4; j++) T[cg * 4 + j][ng * 4 + i] = xn[i][j];
        load_w_t(dWn, Wt, tid);
        __syncthreads();

#pragma unroll
        for (int i = 0; i < 4; i++)
#pragma unroll
            for (int j = 0; j < 4; j++) acc[i][j] = 0.0f;
        GEMM64(acc, T, Wt, cg, ng);

        float4 bn = *(const float4*)&dbn[cg * 4];
#pragma unroll
        for (int i = 0; i < 4; i++) {
            int n = node0 + ng * 4 + i;
            if (n < N_NODES) {
                float4 o;
                o.x = acc[i][0] + bn.x;
                o.y = acc[i][1] + bn.y;
                o.z = acc[i][2] + bn.z;
                o.w = acc[i][3] + bn.w;
                *(float4*)&g_y[(size_t)n * HID + cg * 4] = o;
            }
        }
    }
}

// ---------------- mean pool (batch sorted: segmented flush) -------
__global__ void k_pool(const int* __restrict__ batch) {
    int tid = threadIdx.x;
    int c = tid & 63;
    int grp = tid >> 6;  // 0..3
    long base = (long)blockIdx.x * 64 + grp * 16;
    if (base >= N_NODES) return;

    float acc = 0.0f;
    int cur = -1;
    for (int i = 0; i < 16; i++) {
        long n = base + i;
        if (n >= N_NODES) break;
        int g = __ldg(&batch[n]);
        if (g != cur) {
            if (cur >= 0) atomicAdd(&g_pooled[cur * HID + c], acc);
            cur = g;
            acc = 0.0f;
        }
        acc += g_x[n * HID + c];
    }
    if (cur >= 0) atomicAdd(&g_pooled[cur * HID + c], acc);

    if (c == 0) {
        float cnt = 0.0f;
        int cg2 = -1;
        for (int i = 0; i < 16; i++) {
            long n = base + i;
            if (n >= N_NODES) break;
            int g = __ldg(&batch[n]);
            if (g != cg2) {
                if (cg2 >= 0) atomicAdd(&g_counts[cg2], cnt);
                cg2 = g;
                cnt = 0.0f;
            }
            cnt += 1.0f;
        }
        if (cg2 >= 0) atomicAdd(&g_counts[cg2], cnt);
    }
}

// ---------------- gate MLP + softmax + prediction -----------------
__global__ void k_gate(const float* __restrict__ mlip,
                       const float* __restrict__ gW1, const float* __restrict__ gb1,
                       const float* __restrict__ gW2, const float* __restrict__ gb2,
                       const float* __restrict__ gW3, const float* __restrict__ gb3,
                       float* __restrict__ out) {
    int g = blockIdx.x;
    int c = threadIdx.x;
    __shared__ float in[GATE_IN];
    __shared__ float h1[G1];
    __shared__ float h2[G2];
    __shared__ float lg[N_EXPERTS];

    float cnt = fmaxf(g_counts[g], 1.0f);
    in[c] = g_pooled[g * HID + c] / cnt;
    if (c < N_EXPERTS) in[HID + c] = mlip[g * N_EXPERTS + c];
    __syncthreads();

    float acc = gb1[c];
#pragma unroll
    for (int k = 0; k < GATE_IN; k++) acc += in[k] * gW1[c * GATE_IN + k];
    h1[c] = fmaxf(acc, 0.0f);
    __syncthreads();

    if (c < G2) {
        float a2 = gb2[c];
#pragma unroll
        for (int k = 0; k < G1; k++) a2 += h1[k] * gW2[c * G1 + k];
        h2[c] = fmaxf(a2, 0.0f);
    }
    __syncthreads();

    if (c < N_EXPERTS) {
        float a3 = gb3[c];
#pragma unroll
        for (int k = 0; k < G2; k++) a3 += h2[k] * gW3[c * G2 + k];
        lg[c] = a3;
        out[g * N_EXPERTS + c] = a3;  // logits
    }
    __syncthreads();

    if (c == 0) {
        float m = lg[0];
        for (int k = 1; k < N_EXPERTS; k++) m = fmaxf(m, lg[k]);
        float wts[N_EXPERTS];
        float ssum = 0.0f;
        for (int k = 0; k < N_EXPERTS; k++) { wts[k] = expf(lg[k] - m); ssum += wts[k]; }
        float pred = 0.0f;
        for (int k = 0; k < N_EXPERTS; k++) {
            float wv = wts[k] / ssum;
            out[N_GRAPHS * N_EXPERTS + g * N_EXPERTS + k] = wv;  // weights
            pred += mlip[g * N_EXPERTS + k] * wv;
        }
        out[2 * N_GRAPHS * N_EXPERTS + g] = pred;  // prediction
    }
}

// ---------------- launch ------------------------------------------
extern "C" void kernel_launch(void* const* d_in, const int* in_sizes, int n_in,
                              void* d_out, int out_size) {
    const int* z = (const int*)d_in[0];
    const int* edge_index = (const int*)d_in[1];
    const float* ew = (const float*)d_in[2];
    const int* batch = (const int*)d_in[3];
    const float* mlip = (const float*)d_in[4];
    const float* emb = (const float*)d_in[5];
    const float* fW1 = (const float*)d_in[6];
    const float* fb1 = (const float*)d_in[7];
    const float* fW2 = (const float*)d_in[8];
    const float* fb2 = (const float*)d_in[9];
    const float* dW = (const float*)d_in[10];
    const float* db = (const float*)d_in[11];
    const float* uW1 = (const float*)d_in[12];
    const float* ub1 = (const float*)d_in[13];
    const float* uW2 = (const float*)d_in[14];
    const float* ub2 = (const float*)d_in[15];
    const float* gW1 = (const float*)d_in[16];
    const float* gb1 = (const float*)d_in[17];
    const float* gW2 = (const float*)d_in[18];
    const float* gb2 = (const float*)d_in[19];
    const float* gW3 = (const float*)d_in[20];
    const float* gb3 = (const float*)d_in[21];
    float* out = (float*)d_out;

    // zero hist/pooled/counts
    k_zero<<<(N_NODES + 255) / 256, 256>>>();
    // CSR build
    k_hist<<<(N_EDGES + 255) / 256, 256>>>(edge_index);
    k_scan<<<1, 1024>>>();
    k_scatter<<<(N_EDGES + 255) / 256, 256>>>(edge_index, ew);
    // filter tables + deltas
    {
        dim3 grid(TABLE + 1, N_LAYERS);
        k_tables<<<grid, HID>>>(fW1, fb1, fW2, fb2);
        int total = N_LAYERS * TABLE * HID;
        k_tabdel<<<(total + 255) / 256, 256>>>();
    }

    int node_blocks = (N_NODES + 63) / 64;  // 1563
    int agg_blocks = (N_NODES * 32 + 255) / 256;  // 12500

    // layer 0 y fused with embedding
    k_embed_ylinear<<<node_blocks, 256>>>(z, emb, dW, db);

    // layer 0
    k_agg<<<agg_blocks, 256>>>(0);
    k_update<false><<<node_blocks, 256>>>(uW1, ub1, uW2, ub2, dW + 1 * HID * HID, db + 1 * HID, 0);
    // layer 1
    k_agg<<<agg_blocks, 256>>>(1);
    k_update<false><<<node_blocks, 256>>>(uW1, ub1, uW2, ub2, dW + 2 * HID * HID, db + 2 * HID, 1);
    // layer 2
    k_agg<<<agg_blocks, 256>>>(2);
    k_update<true><<<node_blocks, 256>>>(uW1, ub1, uW2, ub2, (const float*)0, (const float*)0, 2);

    k_pool<<<node_blocks, 256>>>(batch);
    k_gate<<<N_GRAPHS, HID>>>(mlip, gW1, gb1, gW2, gb2, gW3, gb3, out);
}